// round 9
// baseline (speedup 1.0000x reference)
#include <cuda_runtime.h>
#include <cstdint>

// Batched 2nd-order IIR, register-resident chunked superposition (LCH=8).
//   y[t] = b0*u[t] + b1*u[t-1] - a1*y[t-1] - a2*y[t-2]
// Per segment (SEG=2048): 256 threads x 8-sample chunks, all data in registers.
//   pass 1: zero-state recurrence -> chunk tail (d) only
//   scan:   affine Kogge-Stone over tails (M = A^8 powers), redundant
//           cross-warp combine in every warp, carry in thread-0 registers
//   pass 2: rerun recurrence with true entering state -> direct STG
// No smem data staging; smem holds only matrix tables + warp aggregates.

#define LCH      8
#define NTHREADS 256
#define SEG      (NTHREADS * LCH)   // 2048
#define NWARP    (NTHREADS / 32)

__global__ __launch_bounds__(NTHREADS, 6)
void iir_reg_kernel(const float* __restrict__ bco,
                    const float* __restrict__ aco,
                    const float* __restrict__ u,
                    const float* __restrict__ yinit,
                    const float* __restrict__ uinit,
                    float* __restrict__ yout,
                    int T)
{
    __shared__ float4 pwf4[8];        // M^(2^k), (m11,m12,m21,m22)
    __shared__ float4 Ltf4[32];       // M^(l+1)
    __shared__ float2 aggS[2][NWARP]; // warp aggregates, parity double-buffered

    const int row  = blockIdx.x;
    const int tid  = threadIdx.x;
    const int lane = tid & 31;
    const int wid  = tid >> 5;

    const float b0 = bco[0], b1 = bco[1];
    const float a1 = aco[0], a2 = aco[1];

    const float* urow = u + (size_t)row * T;
    float*       yrow = yout + (size_t)row * T;

    // ---- one-time tables (tid 0) ----
    if (tid == 0) {
        // A = [[-a1,-a2],[1,0]]; M = A^LCH via 3 squarings
        float w11 = -a1, w12 = -a2, w21 = 1.f, w22 = 0.f;
        #pragma unroll
        for (int s = 0; s < 3; s++) {
            float n11 = w11 * w11 + w12 * w21;
            float n12 = w11 * w12 + w12 * w22;
            float n21 = w21 * w11 + w22 * w21;
            float n22 = w21 * w12 + w22 * w22;
            w11 = n11; w12 = n12; w21 = n21; w22 = n22;
        }
        const float M11 = w11, M12 = w12, M21 = w21, M22 = w22;
        #pragma unroll
        for (int k = 0; k < 8; k++) {
            pwf4[k] = make_float4(w11, w12, w21, w22);
            float n11 = w11 * w11 + w12 * w21;
            float n12 = w11 * w12 + w12 * w22;
            float n21 = w21 * w11 + w22 * w21;
            float n22 = w21 * w12 + w22 * w22;
            w11 = n11; w12 = n12; w21 = n21; w22 = n22;
        }
        float c11 = M11, c12 = M12, c21 = M21, c22 = M22;
        Ltf4[0] = make_float4(c11, c12, c21, c22);
        for (int l = 1; l < 32; l++) {
            float n11 = M11 * c11 + M12 * c21;
            float n12 = M11 * c12 + M12 * c22;
            float n21 = M21 * c11 + M22 * c21;
            float n22 = M21 * c12 + M22 * c22;
            c11 = n11; c12 = n12; c21 = n21; c22 = n22;
            Ltf4[l] = make_float4(c11, c12, c21, c22);
        }
    }
    __syncthreads();

    const float4 Lt = Ltf4[lane];          // M^(lane+1), permanent
    float carry1 = yinit[2 * row];         // meaningful in thread 0 only
    float carry2 = yinit[2 * row + 1];
    const float u_init0 = uinit[2 * row];

    const int nseg = T / SEG;

    for (int g = 0; g < nseg; g++) {
        const float4* useg4 = (const float4*)(urow + (size_t)g * SEG);

        // ---- load chunk (2 float4, 32B lane stride) ----
        float4 f0 = useg4[2 * tid];
        float4 f1 = useg4[2 * tid + 1];

        float uprev = __shfl_up_sync(0xffffffffu, f1.w, 1);
        if (lane == 0) {
            long gidx = (long)g * SEG + (long)LCH * tid;   // chunk start sample
            uprev = (gidx == 0) ? u_init0 : __ldg(urow + gidx - 1);
        }

        // ---- pass 1: zero-state tails ----
        float t0 = b0 * f0.x + b1 * uprev;
        float t1 = b0 * f0.y + b1 * f0.x - a1 * t0;
        float t2 = b0 * f0.z + b1 * f0.y - a1 * t1 - a2 * t0;
        float t3 = b0 * f0.w + b1 * f0.z - a1 * t2 - a2 * t1;
        float t4 = b0 * f1.x + b1 * f0.w - a1 * t3 - a2 * t2;
        float t5 = b0 * f1.y + b1 * f1.x - a1 * t4 - a2 * t3;
        float t6 = b0 * f1.z + b1 * f1.y - a1 * t5 - a2 * t4;
        float t7 = b0 * f1.w + b1 * f1.z - a1 * t6 - a2 * t5;
        float rs1 = t7, rs2 = t6;

        // thread 0 folds segment-entry state into its tail
        if (tid == 0) {
            float4 m0 = pwf4[0];
            rs1 += m0.x * carry1 + m0.y * carry2;
            rs2 += m0.z * carry1 + m0.w * carry2;
        }

        // ---- intra-warp affine scan (5 levels) ----
        #pragma unroll
        for (int k = 0; k < 5; k++) {
            const float4 mw = pwf4[k];
            int sh = 1 << k;
            float g1 = __shfl_up_sync(0xffffffffu, rs1, sh);
            float g2 = __shfl_up_sync(0xffffffffu, rs2, sh);
            if (lane >= sh) {
                rs1 += mw.x * g1 + mw.y * g2;
                rs2 += mw.z * g1 + mw.w * g2;
            }
        }
        if (lane == 31) aggS[g & 1][wid] = make_float2(rs1, rs2);
        __syncthreads();

        // ---- redundant cross-warp combine (every warp, lanes 0-7) ----
        float q1 = 0.f, q2 = 0.f;
        if (lane < NWARP) {
            float2 a = aggS[g & 1][lane];
            q1 = a.x; q2 = a.y;
        }
        #pragma unroll
        for (int k = 0; k < 3; k++) {
            const float4 mw = pwf4[5 + k];
            int sh = 1 << k;
            float g1 = __shfl_up_sync(0xffffffffu, q1, sh);
            float g2 = __shfl_up_sync(0xffffffffu, q2, sh);
            if (lane >= sh && lane < NWARP) {
                q1 += mw.x * g1 + mw.y * g2;
                q2 += mw.z * g1 + mw.w * g2;
            }
        }
        // segment-exit state (for next segment's fold)
        float cn1 = __shfl_sync(0xffffffffu, q1, NWARP - 1);
        float cn2 = __shfl_sync(0xffffffffu, q2, NWARP - 1);

        // splice warp prefix: full inclusive state after chunk tid
        float full1 = rs1, full2 = rs2;
        float P1 = __shfl_sync(0xffffffffu, q1, (wid > 0) ? (wid - 1) : 0);
        float P2 = __shfl_sync(0xffffffffu, q2, (wid > 0) ? (wid - 1) : 0);
        if (wid > 0) {
            full1 += Lt.x * P1 + Lt.y * P2;
            full2 += Lt.z * P1 + Lt.w * P2;
        }

        // entering state of chunk tid
        float en1 = __shfl_up_sync(0xffffffffu, full1, 1);
        float en2 = __shfl_up_sync(0xffffffffu, full2, 1);
        if (lane == 0) {
            if (wid == 0) { en1 = carry1; en2 = carry2; }
            else          { en1 = P1;     en2 = P2;     }
        }
        carry1 = cn1; carry2 = cn2;   // used by thread 0 next segment

        // ---- pass 2: true recurrence, direct store ----
        float o0 = b0 * f0.x + b1 * uprev - a1 * en1 - a2 * en2;
        float o1 = b0 * f0.y + b1 * f0.x  - a1 * o0  - a2 * en1;
        float o2 = b0 * f0.z + b1 * f0.y  - a1 * o1  - a2 * o0;
        float o3 = b0 * f0.w + b1 * f0.z  - a1 * o2  - a2 * o1;
        float o4 = b0 * f1.x + b1 * f0.w  - a1 * o3  - a2 * o2;
        float o5 = b0 * f1.y + b1 * f1.x  - a1 * o4  - a2 * o3;
        float o6 = b0 * f1.z + b1 * f1.y  - a1 * o5  - a2 * o4;
        float o7 = b0 * f1.w + b1 * f1.z  - a1 * o6  - a2 * o5;

        float4* yseg4 = (float4*)(yrow + (size_t)g * SEG);
        __stcs(yseg4 + 2 * tid,     make_float4(o0, o1, o2, o3));
        __stcs(yseg4 + 2 * tid + 1, make_float4(o4, o5, o6, o7));
        // no end barrier: aggS is parity double-buffered; the next write to
        // aggS[g&1] is two segments away, separated by the g+1 barrier.
    }
}

extern "C" void kernel_launch(void* const* d_in, const int* in_sizes, int n_in,
                              void* d_out, int out_size) {
    const float* bco   = (const float*)d_in[0];  // (n_b)
    const float* aco   = (const float*)d_in[1];  // (n_a)
    const float* u     = (const float*)d_in[2];  // (B, T)
    const float* yinit = (const float*)d_in[3];  // (B, 2)
    const float* uinit = (const float*)d_in[4];  // (B, 2)
    float* yout        = (float*)d_out;          // (B, T)

    const int B = in_sizes[3] / 2;               // y_init is (B, 2)
    const int T = in_sizes[2] / B;               // u_in is (B, T)

    iir_reg_kernel<<<B, NTHREADS>>>(bco, aco, u, yinit, uinit, yout, T);
}